// round 1
// baseline (speedup 1.0000x reference)
#include <cuda_runtime.h>
#include <math.h>

// IDM_43748536877069
// B=8, NV=2048. state: [B, NV*5] (x,y,v,psi,psidot). lengths: [NV].
// Scalars v0, s0, dth, amax, b as 1-element arrays.
// Output: [B, NV] float32 (action).
//
// Math reformulation (exact):
//   ndist(i,j) = dr*cos(atan2(dy,dx)-psi_j) = dx*cos(psi_j) + dy*sin(psi_j)
//   cone       = ndist>0 && ndist^2 > (dx^2+dy^2)*cos^2(20deg)
//   ndv        = dvx*cos(psi_j) + dvy*sin(psi_j)
// so the O(NV^2) loop is pure FMA + compare, no atan2/sqrt.

#define NV 2048
#define EGOS_PER_BLOCK 128
#define SUBS 4
#define THREADS (EGOS_PER_BLOCK * SUBS)   // 512
#define CHUNK (NV / SUBS)                 // 512

__global__ __launch_bounds__(THREADS, 1)
void idm_kernel(const float* __restrict__ state,
                const float* __restrict__ lengths,
                const float* __restrict__ v0p,
                const float* __restrict__ s0p,
                const float* __restrict__ dthp,
                const float* __restrict__ amaxp,
                const float* __restrict__ bp,
                float* __restrict__ out)
{
    __shared__ float2 xy[NV];                       // 16 KB
    __shared__ float2 vpsi[NV];                     // 16 KB
    __shared__ float  pval[SUBS][EGOS_PER_BLOCK];   // 2 KB
    __shared__ int    pidx[SUBS][EGOS_PER_BLOCK];   // 2 KB

    const int blocksPerBatch = NV / EGOS_PER_BLOCK; // 16
    const int b       = blockIdx.x / blocksPerBatch;
    const int egoBase = (blockIdx.x % blocksPerBatch) * EGOS_PER_BLOCK;
    const float* st   = state + (size_t)b * NV * 5;

    // Stage the batch's x,y,v,psi into shared memory.
    for (int i = threadIdx.x; i < NV; i += THREADS) {
        const float* p = st + i * 5;
        xy[i]   = make_float2(p[0], p[1]);
        vpsi[i] = make_float2(p[2], p[3]);
    }
    __syncthreads();

    const int sub = threadIdx.x >> 7;                 // tid / 128 (uniform per warp)
    const int e   = threadIdx.x & (EGOS_PER_BLOCK-1); // ego within block
    const int j   = egoBase + e;

    const float xj = xy[j].x;
    const float yj = xy[j].y;
    const float2 vp = vpsi[j];
    float sj, cj;
    sincosf(vp.y, &sj, &cj);

    const float K = 0.8830222216f;  // cos^2(20 deg)

    float best = __int_as_float(0x7f800000);  // +inf
    int   bi   = 0;

    const int i0 = sub * CHUNK;
    #pragma unroll 8
    for (int t = 0; t < CHUNK; ++t) {
        const int i = i0 + t;
        const float2 c = xy[i];       // warp-uniform address -> LDS broadcast
        const float dx = c.x - xj;
        const float dy = c.y - yj;
        const float nd = fmaf(dx, cj, dy * sj);
        const float r2 = fmaf(dx, dx, dy * dy);
        const bool cone = (nd > 0.0f) && (nd * nd > r2 * K);
        if (cone && nd < best) { best = nd; bi = i; }   // strict < keeps first index
    }
    pval[sub][e] = best;
    pidx[sub][e] = bi;
    __syncthreads();

    // Sub-0 thread of each ego combines partials (ascending sub => first-index tie-break)
    // and computes the epilogue.
    if (threadIdx.x < EGOS_PER_BLOCK) {
        best = pval[0][e];
        bi   = pidx[0][e];
        #pragma unroll
        for (int s2 = 1; s2 < SUBS; ++s2) {
            const float v2 = pval[s2][e];
            if (v2 < best) { best = v2; bi = pidx[s2][e]; }
        }

        const float v0   = v0p[0];
        const float s0   = s0p[0];
        const float dth  = dthp[0];
        const float amax = amaxp[0];
        const float bb   = bp[0];

        const float vj = vp.x;

        // free-road term: amax * (1 - (v/v0)^4)
        const float q  = vj / v0;
        const float q2 = q * q;
        const float afree = amax * (1.0f - q2 * q2);

        float action = afree;
        const float sal = best - lengths[j];
        if (isfinite(sal)) {
            // leader kinematics
            const float2 lp = vpsi[bi];
            float sl, cl;
            sincosf(lp.y, &sl, &cl);
            const float dvx = lp.x * cl - vj * cj;
            const float dvy = lp.x * sl - vj * sj;
            const float ndv = fmaf(dvx, cj, dvy * sj);

            const float sstar = s0 + vj * dth + vj * ndv / (2.0f * sqrtf(amax * bb));
            const float r = sstar / sal;
            action = afree - amax * r * r;
        }
        out[(size_t)b * NV + j] = action;
    }
}

extern "C" void kernel_launch(void* const* d_in, const int* in_sizes, int n_in,
                              void* d_out, int out_size) {
    const float* state   = (const float*)d_in[0];
    const float* lengths = (const float*)d_in[1];
    const float* v0      = (const float*)d_in[2];
    const float* s0      = (const float*)d_in[3];
    const float* dth     = (const float*)d_in[4];
    const float* amax    = (const float*)d_in[5];
    const float* bpar    = (const float*)d_in[6];
    float* out = (float*)d_out;

    const int B = in_sizes[0] / (NV * 5);
    const int grid = B * (NV / EGOS_PER_BLOCK);
    idm_kernel<<<grid, THREADS>>>(state, lengths, v0, s0, dth, amax, bpar, out);
}

// round 3
// speedup vs baseline: 1.1038x; 1.1038x over previous
#include <cuda_runtime.h>
#include <math.h>

// IDM_43748536877069  — B=8, NV=2048 pairwise IDM leader search + epilogue.
//
// Rotated-frame cone test (exact equivalence):
//   u = dx*cos(psi_j) + dy*sin(psi_j)    (longitudinal)
//   w = -dx*sin(psi_j) + dy*cos(psi_j)   (lateral)
//   cone ⟺ |w|*cot(20°) < u             (implies u>0; dx=dy=0 -> false)
// dx,dy are computed EXPLICITLY (not folded into FMA constants) so the
// self-pair gives exactly u=w=0 and is never selected as leader.

#define NV 2048
#define SLOTS 112                      // egos per block
#define SUBS 4                         // candidate-split per ego
#define THREADS (SLOTS * SUBS)         // 448
#define CHUNK (NV / SUBS)              // 512
#define BPB ((NV + SLOTS - 1) / SLOTS) // 19 blocks per batch

__global__ __launch_bounds__(THREADS, 1)
void idm_kernel(const float* __restrict__ state,
                const float* __restrict__ lengths,
                const float* __restrict__ v0p,
                const float* __restrict__ s0p,
                const float* __restrict__ dthp,
                const float* __restrict__ amaxp,
                const float* __restrict__ bp,
                float* __restrict__ out)
{
    __shared__ float2 xy[NV];               // 16 KB
    __shared__ float  pval[SUBS][SLOTS];
    __shared__ int    pidx[SUBS][SLOTS];

    const int b       = blockIdx.x / BPB;
    const int egoBase = (blockIdx.x % BPB) * SLOTS;
    const float* st   = state + (size_t)b * NV * 5;

    // Stage candidate positions for this batch.
    for (int i = threadIdx.x; i < NV; i += THREADS) {
        const float* p = st + i * 5;
        xy[i] = make_float2(p[0], p[1]);
    }
    __syncthreads();

    // lane mapping: sub = tid&3, ego slot e = tid>>2.
    // A warp = 8 egos x 4 subs; inner loop loads xy[4t+sub] -> 4 consecutive
    // smem addresses per warp (conflict-free broadcast).
    const int sub = threadIdx.x & 3;
    const int e   = threadIdx.x >> 2;
    const int j   = egoBase + e;
    const bool valid = (j < NV);
    const int jc  = valid ? j : 0;

    const float xj = xy[jc].x;
    const float yj = xy[jc].y;
    const float psj = __ldg(st + jc * 5 + 3);
    float sj, cj;
    sincosf(psj, &sj, &cj);

    const float COT20 = 2.7474774194546225f;   // 1/tan(20 deg)
    const float scj = cj * COT20;
    const float nsj = -sj * COT20;

    float best = __int_as_float(0x7f800000);   // +inf
    int   bi   = 0;

    if (valid) {
        #pragma unroll 8
        for (int t = 0; t < CHUNK; ++t) {
            const int i = (t << 2) + sub;          // interleaved: i ≡ sub (mod 4)
            const float2 c = xy[i];
            const float dx = c.x - xj;
            const float dy = c.y - yj;
            const float u = fmaf(dx, cj,  dy * sj);     // longitudinal
            const float w = fmaf(dy, scj, dx * nsj);    // lateral * cot20
            const bool ok = (fabsf(w) < u) && (u < best);
            best = ok ? u : best;
            bi   = ok ? i : bi;
        }
    }
    pval[sub][e] = best;
    pidx[sub][e] = bi;
    __syncthreads();

    // One thread per ego combines the 4 interleaved partials (tie -> lower index)
    // and runs the IDM epilogue.
    if (threadIdx.x < SLOTS) {
        const int ee = threadIdx.x;
        const int jj = egoBase + ee;
        if (jj < NV) {
            float bv = pval[0][ee];
            int   bx = pidx[0][ee];
            #pragma unroll
            for (int s = 1; s < SUBS; ++s) {
                const float v2 = pval[s][ee];
                const int   i2 = pidx[s][ee];
                if (v2 < bv || (v2 == bv && i2 < bx)) { bv = v2; bx = i2; }
            }

            const float v0   = v0p[0];
            const float s0   = s0p[0];
            const float dth  = dthp[0];
            const float amax = amaxp[0];
            const float bb   = bp[0];

            const float vje  = __ldg(st + jj * 5 + 2);
            const float psje = __ldg(st + jj * 5 + 3);
            float sje, cje;
            sincosf(psje, &sje, &cje);

            const float q  = vje / v0;
            const float q2 = q * q;
            const float afree = amax * (1.0f - q2 * q2);

            float action = afree;
            const float sal = bv - lengths[jj];
            if (isfinite(sal)) {
                const float vl  = __ldg(st + bx * 5 + 2);
                const float psl = __ldg(st + bx * 5 + 3);
                float sl, cl;
                sincosf(psl, &sl, &cl);
                const float dvx = vl * cl - vje * cje;
                const float dvy = vl * sl - vje * sje;
                const float ndv = fmaf(dvx, cje, dvy * sje);

                const float sstar = s0 + vje * dth
                                  + vje * ndv / (2.0f * sqrtf(amax * bb));
                const float r = sstar / sal;
                action = afree - amax * r * r;
            }
            out[(size_t)b * NV + jj] = action;
        }
    }
}

extern "C" void kernel_launch(void* const* d_in, const int* in_sizes, int n_in,
                              void* d_out, int out_size) {
    const float* state   = (const float*)d_in[0];
    const float* lengths = (const float*)d_in[1];
    const float* v0      = (const float*)d_in[2];
    const float* s0      = (const float*)d_in[3];
    const float* dth     = (const float*)d_in[4];
    const float* amax    = (const float*)d_in[5];
    const float* bpar    = (const float*)d_in[6];
    float* out = (float*)d_out;

    const int B = in_sizes[0] / (NV * 5);
    const int grid = B * BPB;    // 8 * 19 = 152 == #SMs on GB300
    idm_kernel<<<grid, THREADS>>>(state, lengths, v0, s0, dth, amax, bpar, out);
}

// round 4
// speedup vs baseline: 1.3719x; 1.2429x over previous
#include <cuda_runtime.h>
#include <math.h>

// IDM_43748536877069  — B=8, NV=2048 pairwise IDM leader search + epilogue.
//
// Rotated-frame cone test (exact equivalence):
//   u = dx*cos(psi_j) + dy*sin(psi_j)    (longitudinal)
//   w = -dx*sin(psi_j) + dy*cos(psi_j)   (lateral)
//   cone ⟺ |w|*cot(20°) < u             (implies u>0; dx=dy=0 -> false)
// dx,dy computed explicitly so the self-pair is exactly (0,0) -> never leader.
//
// R4: 896 threads (28 warps/SM, grid=152=1 block/SM), 8 subs per ego,
// float4 candidate loads (2 candidates per LDS.128).

#define NV 2048
#define SLOTS 112                      // egos per block
#define SUBS 8                         // candidate-split per ego
#define THREADS (SLOTS * SUBS)         // 896
#define PAIRS (NV / 2)                 // 1024 float4-packed candidate pairs
#define PCHUNK (PAIRS / SUBS)          // 128 pairs per thread
#define BPB ((NV + SLOTS - 1) / SLOTS) // 19 blocks per batch

__global__ __launch_bounds__(THREADS, 1)
void idm_kernel(const float* __restrict__ state,
                const float* __restrict__ lengths,
                const float* __restrict__ v0p,
                const float* __restrict__ s0p,
                const float* __restrict__ dthp,
                const float* __restrict__ amaxp,
                const float* __restrict__ bp,
                float* __restrict__ out)
{
    __shared__ float4 xy4[PAIRS];            // 16 KB: (x0,y0,x1,y1) per pair
    __shared__ float  pval[SUBS][SLOTS];     // 3.5 KB
    __shared__ int    pidx[SUBS][SLOTS];     // 3.5 KB

    const int b       = blockIdx.x / BPB;
    const int egoBase = (blockIdx.x % BPB) * SLOTS;
    const float* st   = state + (size_t)b * NV * 5;

    // Stage candidate positions, packed two per float4.
    for (int p = threadIdx.x; p < PAIRS; p += THREADS) {
        const float* a = st + (2 * p) * 5;
        xy4[p] = make_float4(a[0], a[1], a[5], a[6]);
    }
    __syncthreads();

    // lane mapping: sub = tid&7, ego slot e = tid>>3.
    // A warp = 4 egos x 8 subs; loop loads xy4[8t+sub] -> 8 consecutive
    // float4 smem addresses per warp (128B, conflict-free, 4-lane broadcast).
    const int sub = threadIdx.x & 7;
    const int e   = threadIdx.x >> 3;
    const int j   = egoBase + e;
    const bool valid = (j < NV);
    const int jc  = valid ? j : 0;

    const float4 cj0 = xy4[jc >> 1];
    const float xj = (jc & 1) ? cj0.z : cj0.x;
    const float yj = (jc & 1) ? cj0.w : cj0.y;
    const float psj = __ldg(st + jc * 5 + 3);
    float sj, cjv;
    sincosf(psj, &sj, &cjv);

    const float COT20 = 2.7474774194546225f;   // 1/tan(20 deg)
    const float scj = cjv * COT20;
    const float nsj = -sj * COT20;

    float best = __int_as_float(0x7f800000);   // +inf
    int   bi   = 0;

    if (valid) {
        #pragma unroll 4
        for (int t = 0; t < PCHUNK; ++t) {
            const int p = (t << 3) + sub;        // pair index, p ≡ sub (mod 8)
            const float4 c = xy4[p];
            const int i0 = p << 1;

            // candidate i0
            const float dx0 = c.x - xj;
            const float dy0 = c.y - yj;
            const float u0  = fmaf(dx0, cjv, dy0 * sj);
            const float w0  = fmaf(dy0, scj, dx0 * nsj);
            // candidate i0+1
            const float dx1 = c.z - xj;
            const float dy1 = c.w - yj;
            const float u1  = fmaf(dx1, cjv, dy1 * sj);
            const float w1  = fmaf(dy1, scj, dx1 * nsj);

            const bool ok0 = (fabsf(w0) < u0) && (u0 < best);
            best = ok0 ? u0 : best;
            bi   = ok0 ? i0 : bi;
            const bool ok1 = (fabsf(w1) < u1) && (u1 < best);
            best = ok1 ? u1 : best;
            bi   = ok1 ? (i0 + 1) : bi;
        }
    }
    pval[sub][e] = best;
    pidx[sub][e] = bi;
    __syncthreads();

    // One thread per ego combines the 8 partials (tie -> lower index),
    // then runs the IDM epilogue.
    if (threadIdx.x < SLOTS) {
        const int ee = threadIdx.x;
        const int jj = egoBase + ee;
        if (jj < NV) {
            float bv = pval[0][ee];
            int   bx = pidx[0][ee];
            #pragma unroll
            for (int s = 1; s < SUBS; ++s) {
                const float v2 = pval[s][ee];
                const int   i2 = pidx[s][ee];
                if (v2 < bv || (v2 == bv && i2 < bx)) { bv = v2; bx = i2; }
            }

            const float v0   = v0p[0];
            const float s0   = s0p[0];
            const float dth  = dthp[0];
            const float amax = amaxp[0];
            const float bb   = bp[0];

            const float vje  = __ldg(st + jj * 5 + 2);
            const float psje = __ldg(st + jj * 5 + 3);
            float sje, cje;
            sincosf(psje, &sje, &cje);

            const float q  = vje / v0;
            const float q2 = q * q;
            const float afree = amax * (1.0f - q2 * q2);

            float action = afree;
            const float sal = bv - lengths[jj];
            if (isfinite(sal)) {
                const float vl  = __ldg(st + bx * 5 + 2);
                const float psl = __ldg(st + bx * 5 + 3);
                float sl, cl;
                sincosf(psl, &sl, &cl);
                const float dvx = vl * cl - vje * cje;
                const float dvy = vl * sl - vje * sje;
                const float ndv = fmaf(dvx, cje, dvy * sje);

                const float sstar = s0 + vje * dth
                                  + vje * ndv / (2.0f * sqrtf(amax * bb));
                const float r = sstar / sal;
                action = afree - amax * r * r;
            }
            out[(size_t)b * NV + jj] = action;
        }
    }
}

extern "C" void kernel_launch(void* const* d_in, const int* in_sizes, int n_in,
                              void* d_out, int out_size) {
    const float* state   = (const float*)d_in[0];
    const float* lengths = (const float*)d_in[1];
    const float* v0      = (const float*)d_in[2];
    const float* s0      = (const float*)d_in[3];
    const float* dth     = (const float*)d_in[4];
    const float* amax    = (const float*)d_in[5];
    const float* bpar    = (const float*)d_in[6];
    float* out = (float*)d_out;

    const int B = in_sizes[0] / (NV * 5);
    const int grid = B * BPB;    // 8 * 19 = 152 == #SMs on GB300
    idm_kernel<<<grid, THREADS>>>(state, lengths, v0, s0, dth, amax, bpar, out);
}